// round 12
// baseline (speedup 1.0000x reference)
#include <cuda_runtime.h>
#include <cuda_bf16.h>
#include <cstdint>
#include <math.h>

#define N_NODES 50000
#define D_FEAT  512
#define FILTERS 256
#define NCLS    16
#define E_MAX   1600000

#define TILE_M  128
#define N_PAD   50048            // 391 * 128
#define N_TILES 391
#define NK      48               // 3 terms * (512/32) k-chunks of 32

// ---------------- scratch (device globals; no allocations allowed) ----------
__device__ float g_y1  [(size_t)N_NODES * FILTERS];
__device__ float g_y2  [(size_t)N_NODES * NCLS];
__device__ __nv_bfloat16 g_Xhi [(size_t)N_PAD * D_FEAT];
__device__ __nv_bfloat16 g_Xlo [(size_t)N_PAD * D_FEAT];
__device__ __nv_bfloat16 g_W1Thi[(size_t)FILTERS * D_FEAT];   // [n][k]
__device__ __nv_bfloat16 g_W1Tlo[(size_t)FILTERS * D_FEAT];
// CSR (by dst)
__device__ int   g_deg   [N_NODES];
__device__ int   g_fill  [N_NODES];
__device__ int   g_rowptr[N_NODES + 1];
__device__ int   g_csrc  [E_MAX];
__device__ float g_cw    [E_MAX];

// ============================ helpers ========================================
__device__ __forceinline__ uint32_t smem_u32(const void* p) {
    uint32_t a;
    asm("{ .reg .u64 t; cvta.to.shared.u64 t, %1; cvt.u32.u64 %0, t; }" : "=r"(a) : "l"(p));
    return a;
}
__device__ __forceinline__ void cp16(uint32_t saddr, const void* g) {
    asm volatile("cp.async.cg.shared.global [%0], [%1], 16;" :: "r"(saddr), "l"(g));
}
__device__ __forceinline__ void ldm_x4(uint32_t& r0, uint32_t& r1, uint32_t& r2, uint32_t& r3,
                                       uint32_t addr) {
    asm volatile("ldmatrix.sync.aligned.m8n8.x4.shared.b16 {%0,%1,%2,%3}, [%4];"
                 : "=r"(r0), "=r"(r1), "=r"(r2), "=r"(r3) : "r"(addr));
}
__device__ __forceinline__ void mma_bf16(float& c0, float& c1, float& c2, float& c3,
                                         uint32_t a0, uint32_t a1, uint32_t a2, uint32_t a3,
                                         uint32_t b0, uint32_t b1) {
    asm volatile("mma.sync.aligned.m16n8k16.row.col.f32.bf16.bf16.f32 "
                 "{%0,%1,%2,%3}, {%4,%5,%6,%7}, {%8,%9}, {%0,%1,%2,%3};"
                 : "+f"(c0), "+f"(c1), "+f"(c2), "+f"(c3)
                 : "r"(a0), "r"(a1), "r"(a2), "r"(a3), "r"(b0), "r"(b1));
}

// ---------------- split/convert kernels -------------------------------------
__global__ __launch_bounds__(256)
void conv_x_kernel(const float* __restrict__ X) {
    size_t i4 = (size_t)blockIdx.x * 256 + threadIdx.x;
    size_t base = i4 * 4;
    if (base >= (size_t)N_PAD * D_FEAT) return;
    __nv_bfloat16 h[4], l[4];
    if (base < (size_t)N_NODES * D_FEAT) {
        float4 v = *reinterpret_cast<const float4*>(X + base);
        float vv[4] = {v.x, v.y, v.z, v.w};
        #pragma unroll
        for (int j = 0; j < 4; j++) {
            h[j] = __float2bfloat16_rn(vv[j]);
            l[j] = __float2bfloat16_rn(vv[j] - __bfloat162float(h[j]));
        }
    } else {
        #pragma unroll
        for (int j = 0; j < 4; j++) { h[j] = __float2bfloat16(0.f); l[j] = h[j]; }
    }
    *reinterpret_cast<__nv_bfloat162*>(g_Xhi + base)     = __halves2bfloat162(h[0], h[1]);
    *reinterpret_cast<__nv_bfloat162*>(g_Xhi + base + 2) = __halves2bfloat162(h[2], h[3]);
    *reinterpret_cast<__nv_bfloat162*>(g_Xlo + base)     = __halves2bfloat162(l[0], l[1]);
    *reinterpret_cast<__nv_bfloat162*>(g_Xlo + base + 2) = __halves2bfloat162(l[2], l[3]);
}

__global__ __launch_bounds__(256)
void conv_w1_kernel(const float* __restrict__ W1) {
    int i = blockIdx.x * 256 + threadIdx.x;
    if (i >= D_FEAT * FILTERS) return;
    int k = i >> 8;
    int n = i & (FILTERS - 1);
    float v = W1[i];
    __nv_bfloat16 h = __float2bfloat16_rn(v);
    __nv_bfloat16 l = __float2bfloat16_rn(v - __bfloat162float(h));
    g_W1Thi[(size_t)n * D_FEAT + k] = h;
    g_W1Tlo[(size_t)n * D_FEAT + k] = l;
}

// ---------------- GEMM1 via mma.sync bf16 (unchanged, proven) ----------------
#define LDK 40

__device__ __forceinline__ void fill_stage(int i, size_t m0, int bn0,
                                           uint32_t sA, uint32_t sB, int tid) {
    int term = i >> 4;
    int k0 = (i & 15) * 32;
    const __nv_bfloat16* A = (term < 2) ? g_Xhi : g_Xlo;
    const __nv_bfloat16* B = (term == 1) ? g_W1Tlo : g_W1Thi;
    int r = tid >> 2, c = tid & 3;
    #pragma unroll
    for (int t = 0; t < 2; t++) {
        int row = r + t * 64;
        cp16(sA + (uint32_t)(row * LDK + c * 8) * 2,
             A + (m0 + row) * D_FEAT + k0 + c * 8);
        cp16(sB + (uint32_t)(row * LDK + c * 8) * 2,
             B + (size_t)(bn0 + row) * D_FEAT + k0 + c * 8);
    }
    asm volatile("cp.async.commit_group;" ::: "memory");
}

__global__ __launch_bounds__(256)
void gemm1_mma_kernel() {
    __shared__ __align__(16) __nv_bfloat16 As[2][128 * LDK];
    __shared__ __align__(16) __nv_bfloat16 Bs[2][128 * LDK];

    const int tid  = threadIdx.x;
    const int wid  = tid >> 5;
    const int lane = tid & 31;
    const int wm   = wid >> 2;
    const int wn   = wid & 3;
    const size_t m0 = (size_t)blockIdx.x * TILE_M;
    const int bn0   = blockIdx.y * 128;

    const uint32_t sA0 = smem_u32(As[0]);
    const uint32_t sA1 = smem_u32(As[1]);
    const uint32_t sB0 = smem_u32(Bs[0]);
    const uint32_t sB1 = smem_u32(Bs[1]);

    const int lrow8 = lane & 7;
    const int lmat  = lane >> 3;
    const int a_r = lrow8 + (lmat & 1) * 8;
    const int a_k = (lmat >> 1) * 8;
    const int b_n = lrow8 + (lmat >> 1) * 8;
    const int b_k = (lmat & 1) * 8;

    const uint32_t aoff = (uint32_t)((wm * 64 + a_r) * LDK + a_k) * 2;
    const uint32_t boff = (uint32_t)((wn * 32 + b_n) * LDK + b_k) * 2;

    float c[4][4][4];
    #pragma unroll
    for (int mi = 0; mi < 4; mi++)
        #pragma unroll
        for (int ni = 0; ni < 4; ni++)
            #pragma unroll
            for (int j = 0; j < 4; j++) c[mi][ni][j] = 0.f;

    fill_stage(0, m0, bn0, sA0, sB0, tid);

    for (int i = 0; i < NK; i++) {
        const int s = i & 1;
        if (i + 1 < NK) {
            fill_stage(i + 1, m0, bn0, s ? sA0 : sA1, s ? sB0 : sB1, tid);
            asm volatile("cp.async.wait_group 1;" ::: "memory");
        } else {
            asm volatile("cp.async.wait_group 0;" ::: "memory");
        }
        __syncthreads();

        const uint32_t cA = (s ? sA1 : sA0) + aoff;
        const uint32_t cB = (s ? sB1 : sB0) + boff;

        #pragma unroll
        for (int h = 0; h < 2; h++) {
            uint32_t a[4][4];
            uint32_t b[2][4];
            #pragma unroll
            for (int mi = 0; mi < 4; mi++)
                ldm_x4(a[mi][0], a[mi][1], a[mi][2], a[mi][3],
                       cA + h * 32 + (uint32_t)mi * (16 * LDK * 2));
            #pragma unroll
            for (int p = 0; p < 2; p++)
                ldm_x4(b[p][0], b[p][1], b[p][2], b[p][3],
                       cB + h * 32 + (uint32_t)p * (16 * LDK * 2));
            #pragma unroll
            for (int mi = 0; mi < 4; mi++) {
                #pragma unroll
                for (int ni = 0; ni < 4; ni++) {
                    uint32_t bb0 = (ni & 1) ? b[ni >> 1][2] : b[ni >> 1][0];
                    uint32_t bb1 = (ni & 1) ? b[ni >> 1][3] : b[ni >> 1][1];
                    mma_bf16(c[mi][ni][0], c[mi][ni][1], c[mi][ni][2], c[mi][ni][3],
                             a[mi][0], a[mi][1], a[mi][2], a[mi][3], bb0, bb1);
                }
            }
        }
        __syncthreads();
    }

    const int rr = lane >> 2;
    const int cc = (lane & 3) * 2;
    #pragma unroll
    for (int mi = 0; mi < 4; mi++) {
        size_t row0 = m0 + wm * 64 + mi * 16 + rr;
        #pragma unroll
        for (int ni = 0; ni < 4; ni++) {
            int col = bn0 + wn * 32 + ni * 8 + cc;
            if (row0 < N_NODES)
                *reinterpret_cast<float2*>(g_y1 + row0 * FILTERS + col) =
                    make_float2(c[mi][ni][0], c[mi][ni][1]);
            if (row0 + 8 < N_NODES)
                *reinterpret_cast<float2*>(g_y1 + (row0 + 8) * FILTERS + col) =
                    make_float2(c[mi][ni][2], c[mi][ni][3]);
        }
    }
}

// ---------------- CSR build ---------------------------------------------------
__global__ void csr_zero_kernel() {
    int i = blockIdx.x * blockDim.x + threadIdx.x;
    if (i < N_NODES) { g_deg[i] = 0; g_fill[i] = 0; }
}

__global__ void csr_hist_kernel(const int* __restrict__ edst, int E) {
    int e = blockIdx.x * blockDim.x + threadIdx.x;
    if (e < E) atomicAdd(&g_deg[edst[e]], 1);
}

__global__ __launch_bounds__(1024)
void csr_scan_kernel() {
    __shared__ int sums[1024];
    const int t = threadIdx.x;
    const int CH = (N_NODES + 1023) / 1024;
    int beg = t * CH;
    int end = min(beg + CH, N_NODES);
    int s = 0;
    for (int i = beg; i < end; i++) s += g_deg[i];
    sums[t] = s;
    __syncthreads();
    #pragma unroll
    for (int off = 1; off < 1024; off <<= 1) {
        int v = 0;
        if (t >= off) v = sums[t - off];
        __syncthreads();
        if (t >= off) sums[t] += v;
        __syncthreads();
    }
    int pre = (t == 0) ? 0 : sums[t - 1];
    for (int i = beg; i < end; i++) {
        int d = g_deg[i];
        g_rowptr[i] = pre;
        pre += d;
    }
    if (t == 1023) g_rowptr[N_NODES] = pre;
}

__global__ void csr_fill_kernel(const int* __restrict__ esrc, const int* __restrict__ edst,
                                const float* __restrict__ ew, int E) {
    int e = blockIdx.x * blockDim.x + threadIdx.x;
    if (e >= E) return;
    int d = edst[e];
    int pos = g_rowptr[d] + atomicAdd(&g_fill[d], 1);
    g_csrc[pos] = esrc[e];
    g_cw[pos]   = ew[e];
}

// ---------------- fused: spmm1 (CSR gather) + ReLU + @W2 -> y2 ---------------
// Warp per dst. acc1 row lives entirely in registers; never touches memory.
__global__ __launch_bounds__(256)
void spmm1_gemm2_kernel(const float* __restrict__ W2) {
    __shared__ float4 sW2[FILTERS * 4];          // sW2[f*4 + c4] = W2[f][c4*4..+3]

    const int tid = threadIdx.x;
    // stage W2 (coalesced, no conflicts on store)
    #pragma unroll
    for (int t = 0; t < 4; t++) {
        int i = tid + t * 256;                   // 1024 float4
        sW2[i] = reinterpret_cast<const float4*>(W2)[i];
    }
    __syncthreads();

    int dst  = (blockIdx.x * blockDim.x + tid) >> 5;
    int lane = tid & 31;
    if (dst >= N_NODES) return;
    int e   = g_rowptr[dst];
    int end = g_rowptr[dst + 1];

    float4 a0 = make_float4(0.f, 0.f, 0.f, 0.f);
    float4 a1 = a0, b0 = a0, b1 = a0;

    for (; e + 1 < end; e += 2) {
        int   s0 = __ldg(g_csrc + e),     s1 = __ldg(g_csrc + e + 1);
        float w0 = __ldg(g_cw + e),       w1 = __ldg(g_cw + e + 1);
        const float4* r0 = reinterpret_cast<const float4*>(g_y1 + (size_t)s0 * FILTERS);
        const float4* r1 = reinterpret_cast<const float4*>(g_y1 + (size_t)s1 * FILTERS);
        float4 v00 = r0[lane], v01 = r0[lane + 32];
        float4 v10 = r1[lane], v11 = r1[lane + 32];
        a0.x += w0 * v00.x; a0.y += w0 * v00.y; a0.z += w0 * v00.z; a0.w += w0 * v00.w;
        a1.x += w0 * v01.x; a1.y += w0 * v01.y; a1.z += w0 * v01.z; a1.w += w0 * v01.w;
        b0.x += w1 * v10.x; b0.y += w1 * v10.y; b0.z += w1 * v10.z; b0.w += w1 * v10.w;
        b1.x += w1 * v11.x; b1.y += w1 * v11.y; b1.z += w1 * v11.z; b1.w += w1 * v11.w;
    }
    if (e < end) {
        int   s0 = __ldg(g_csrc + e);
        float w0 = __ldg(g_cw + e);
        const float4* r0 = reinterpret_cast<const float4*>(g_y1 + (size_t)s0 * FILTERS);
        float4 v00 = r0[lane], v01 = r0[lane + 32];
        a0.x += w0 * v00.x; a0.y += w0 * v00.y; a0.z += w0 * v00.z; a0.w += w0 * v00.w;
        a1.x += w0 * v01.x; a1.y += w0 * v01.y; a1.z += w0 * v01.z; a1.w += w0 * v01.w;
    }
    // merge + ReLU: lane holds h[f] for f = 4*lane+j (h0) and 128+4*lane+j (h1)
    float h0[4], h1[4];
    h0[0] = fmaxf(a0.x + b0.x, 0.f); h0[1] = fmaxf(a0.y + b0.y, 0.f);
    h0[2] = fmaxf(a0.z + b0.z, 0.f); h0[3] = fmaxf(a0.w + b0.w, 0.f);
    h1[0] = fmaxf(a1.x + b1.x, 0.f); h1[1] = fmaxf(a1.y + b1.y, 0.f);
    h1[2] = fmaxf(a1.z + b1.z, 0.f); h1[3] = fmaxf(a1.w + b1.w, 0.f);

    // per-lane 16-class partials: p[c] = sum_{f in lane set} h[f] * W2[f][c]
    float p[16];
    #pragma unroll
    for (int c = 0; c < 16; c++) p[c] = 0.f;
    #pragma unroll
    for (int j = 0; j < 4; j++) {
        int f0 = 4 * lane + j;
        int f1 = f0 + 128;
        #pragma unroll
        for (int c4 = 0; c4 < 4; c4++) {
            float4 w = sW2[f0 * 4 + c4];
            p[c4*4+0] += h0[j] * w.x; p[c4*4+1] += h0[j] * w.y;
            p[c4*4+2] += h0[j] * w.z; p[c4*4+3] += h0[j] * w.w;
            float4 u = sW2[f1 * 4 + c4];
            p[c4*4+0] += h1[j] * u.x; p[c4*4+1] += h1[j] * u.y;
            p[c4*4+2] += h1[j] * u.z; p[c4*4+3] += h1[j] * u.w;
        }
    }

    // cross-lane reduce with value splitting: 31 shfl total.
    const unsigned FULL = 0xFFFFFFFFu;
    #pragma unroll
    for (int c = 0; c < 16; c++) p[c] += __shfl_xor_sync(FULL, p[c], 16);
    float v1[8];
    {
        int b = (lane >> 3) & 1;
        #pragma unroll
        for (int k = 0; k < 8; k++) {
            float s = b ? p[k] : p[k + 8];          // send what partner keeps
            float r = __shfl_xor_sync(FULL, s, 8);
            v1[k] = (b ? p[k + 8] : p[k]) + r;
        }
    }
    float v2[4];
    {
        int b = (lane >> 2) & 1;
        #pragma unroll
        for (int k = 0; k < 4; k++) {
            float s = b ? v1[k] : v1[k + 4];
            float r = __shfl_xor_sync(FULL, s, 4);
            v2[k] = (b ? v1[k + 4] : v1[k]) + r;
        }
    }
    float v3[2];
    {
        int b = (lane >> 1) & 1;
        #pragma unroll
        for (int k = 0; k < 2; k++) {
            float s = b ? v2[k] : v2[k + 2];
            float r = __shfl_xor_sync(FULL, s, 2);
            v3[k] = (b ? v2[k + 2] : v2[k]) + r;
        }
    }
    float v4;
    {
        int b = lane & 1;
        float s = b ? v3[0] : v3[1];
        float r = __shfl_xor_sync(FULL, s, 1);
        v4 = (b ? v3[1] : v3[0]) + r;
    }
    // lane l now holds class (l & 15); lanes 0..15 write the row
    if (lane < 16)
        g_y2[(size_t)dst * NCLS + lane] = v4;
}

// ---------------- spmm2 (CSR gather) + fused softmax -------------------------
__global__ __launch_bounds__(256)
void spmm2_softmax_kernel(float* __restrict__ out) {
    int hw  = (blockIdx.x * blockDim.x + threadIdx.x) >> 4;
    int l   = threadIdx.x & 15;
    if (hw >= N_NODES) return;
    int e   = g_rowptr[hw];
    int end = g_rowptr[hw + 1];

    float acc = 0.f;
    for (; e < end; e++) {
        int   s = __ldg(g_csrc + e);
        float w = __ldg(g_cw + e);
        acc += w * __ldg(g_y2 + (size_t)s * NCLS + l);
    }

    float m = acc;
    #pragma unroll
    for (int off = 8; off >= 1; off >>= 1)
        m = fmaxf(m, __shfl_xor_sync(0xFFFFFFFFu, m, off, 16));
    float ev = expf(acc - m);
    float sum = ev;
    #pragma unroll
    for (int off = 8; off >= 1; off >>= 1)
        sum += __shfl_xor_sync(0xFFFFFFFFu, sum, off, 16);
    out[(size_t)hw * NCLS + l] = ev / sum;
}

// ---------------- launch ------------------------------------------------------
extern "C" void kernel_launch(void* const* d_in, const int* in_sizes, int n_in,
                              void* d_out, int out_size) {
    const float* x   = (const float*)d_in[0];
    const float* W1  = (const float*)d_in[1];
    const float* W2  = (const float*)d_in[2];
    const float* ew  = (const float*)d_in[3];
    const int*   es  = (const int*)  d_in[4];
    const int*   ed  = (const int*)  d_in[5];
    const int E = in_sizes[3];
    float* out = (float*)d_out;

    // split X and W1^T into bf16 hi/lo
    {
        size_t n4 = ((size_t)N_PAD * D_FEAT) / 4;
        conv_x_kernel<<<(unsigned)((n4 + 255) / 256), 256>>>(x);
        conv_w1_kernel<<<(D_FEAT * FILTERS + 255) / 256, 256>>>(W1);
    }

    // CSR build
    csr_zero_kernel<<<(N_NODES + 255) / 256, 256>>>();
    csr_hist_kernel<<<(E + 255) / 256, 256>>>(ed, E);
    csr_scan_kernel<<<1, 1024>>>();
    csr_fill_kernel<<<(E + 255) / 256, 256>>>(es, ed, ew, E);

    // GEMM1 on HMMA: y1 = Xhi@W1hi + Xhi@W1lo + Xlo@W1hi
    {
        dim3 grid(N_TILES, 2);
        gemm1_mma_kernel<<<grid, 256>>>();
    }

    // fused layer-1 propagate + ReLU + GEMM2 -> y2 (no acc1, no atomics)
    spmm1_gemm2_kernel<<<(N_NODES * 32 + 255) / 256, 256>>>(W2);

    // layer-2 propagate + softmax, single write of output
    spmm2_softmax_kernel<<<(N_NODES * 16 + 255) / 256, 256>>>(out);
}

// round 17
// speedup vs baseline: 1.2417x; 1.2417x over previous
#include <cuda_runtime.h>
#include <cuda_bf16.h>
#include <cstdint>
#include <math.h>

#define N_NODES 50000
#define D_FEAT  512
#define FILTERS 256
#define NCLS    16
#define E_MAX   1600000

#define TILE_M  128
#define N_PAD   50048            // 391 * 128
#define N_TILES 391
#define NK      48               // 3 terms * (512/32) k-chunks of 32

// ---------------- scratch (device globals; no allocations allowed) ----------
__device__ float g_y1  [(size_t)N_NODES * FILTERS];
__device__ float g_acc1[(size_t)N_NODES * FILTERS];
__device__ float g_y2  [(size_t)N_NODES * NCLS];
__device__ __nv_bfloat16 g_Xhi [(size_t)N_PAD * D_FEAT];
__device__ __nv_bfloat16 g_Xlo [(size_t)N_PAD * D_FEAT];
__device__ __nv_bfloat16 g_W1Thi[(size_t)FILTERS * D_FEAT];   // [n][k]
__device__ __nv_bfloat16 g_W1Tlo[(size_t)FILTERS * D_FEAT];
// CSR (by dst)
__device__ int   g_deg   [N_NODES];
__device__ int   g_fill  [N_NODES];
__device__ int   g_rowptr[N_NODES + 1];
__device__ int   g_csrc  [E_MAX];
__device__ float g_cw    [E_MAX];

// ============================ helpers ========================================
__device__ __forceinline__ uint32_t smem_u32(const void* p) {
    uint32_t a;
    asm("{ .reg .u64 t; cvta.to.shared.u64 t, %1; cvt.u32.u64 %0, t; }" : "=r"(a) : "l"(p));
    return a;
}
__device__ __forceinline__ void cp16(uint32_t saddr, const void* g) {
    asm volatile("cp.async.cg.shared.global [%0], [%1], 16;" :: "r"(saddr), "l"(g));
}
__device__ __forceinline__ void ldm_x4(uint32_t& r0, uint32_t& r1, uint32_t& r2, uint32_t& r3,
                                       uint32_t addr) {
    asm volatile("ldmatrix.sync.aligned.m8n8.x4.shared.b16 {%0,%1,%2,%3}, [%4];"
                 : "=r"(r0), "=r"(r1), "=r"(r2), "=r"(r3) : "r"(addr));
}
__device__ __forceinline__ void mma_bf16(float& c0, float& c1, float& c2, float& c3,
                                         uint32_t a0, uint32_t a1, uint32_t a2, uint32_t a3,
                                         uint32_t b0, uint32_t b1) {
    asm volatile("mma.sync.aligned.m16n8k16.row.col.f32.bf16.bf16.f32 "
                 "{%0,%1,%2,%3}, {%4,%5,%6,%7}, {%8,%9}, {%0,%1,%2,%3};"
                 : "+f"(c0), "+f"(c1), "+f"(c2), "+f"(c3)
                 : "r"(a0), "r"(a1), "r"(a2), "r"(a3), "r"(b0), "r"(b1));
}

// ---------------- split/convert kernels -------------------------------------
__global__ __launch_bounds__(256)
void conv_x_kernel(const float* __restrict__ X) {
    size_t i4 = (size_t)blockIdx.x * 256 + threadIdx.x;
    size_t base = i4 * 4;
    if (base >= (size_t)N_PAD * D_FEAT) return;
    __nv_bfloat16 h[4], l[4];
    if (base < (size_t)N_NODES * D_FEAT) {
        float4 v = *reinterpret_cast<const float4*>(X + base);
        float vv[4] = {v.x, v.y, v.z, v.w};
        #pragma unroll
        for (int j = 0; j < 4; j++) {
            h[j] = __float2bfloat16_rn(vv[j]);
            l[j] = __float2bfloat16_rn(vv[j] - __bfloat162float(h[j]));
        }
    } else {
        #pragma unroll
        for (int j = 0; j < 4; j++) { h[j] = __float2bfloat16(0.f); l[j] = h[j]; }
    }
    *reinterpret_cast<__nv_bfloat162*>(g_Xhi + base)     = __halves2bfloat162(h[0], h[1]);
    *reinterpret_cast<__nv_bfloat162*>(g_Xhi + base + 2) = __halves2bfloat162(h[2], h[3]);
    *reinterpret_cast<__nv_bfloat162*>(g_Xlo + base)     = __halves2bfloat162(l[0], l[1]);
    *reinterpret_cast<__nv_bfloat162*>(g_Xlo + base + 2) = __halves2bfloat162(l[2], l[3]);
}

__global__ __launch_bounds__(256)
void conv_w1_kernel(const float* __restrict__ W1) {
    int i = blockIdx.x * 256 + threadIdx.x;
    if (i >= D_FEAT * FILTERS) return;
    int k = i >> 8;
    int n = i & (FILTERS - 1);
    float v = W1[i];
    __nv_bfloat16 h = __float2bfloat16_rn(v);
    __nv_bfloat16 l = __float2bfloat16_rn(v - __bfloat162float(h));
    g_W1Thi[(size_t)n * D_FEAT + k] = h;
    g_W1Tlo[(size_t)n * D_FEAT + k] = l;
}

// ---------------- GEMM1 via mma.sync bf16 ------------------------------------
#define LDK 40

__device__ __forceinline__ void fill_stage(int i, size_t m0, int bn0,
                                           uint32_t sA, uint32_t sB, int tid) {
    int term = i >> 4;
    int k0 = (i & 15) * 32;
    const __nv_bfloat16* A = (term < 2) ? g_Xhi : g_Xlo;
    const __nv_bfloat16* B = (term == 1) ? g_W1Tlo : g_W1Thi;
    int r = tid >> 2, c = tid & 3;
    #pragma unroll
    for (int t = 0; t < 2; t++) {
        int row = r + t * 64;
        cp16(sA + (uint32_t)(row * LDK + c * 8) * 2,
             A + (m0 + row) * D_FEAT + k0 + c * 8);
        cp16(sB + (uint32_t)(row * LDK + c * 8) * 2,
             B + (size_t)(bn0 + row) * D_FEAT + k0 + c * 8);
    }
    asm volatile("cp.async.commit_group;" ::: "memory");
}

__global__ __launch_bounds__(256)
void gemm1_mma_kernel() {
    __shared__ __align__(16) __nv_bfloat16 As[2][128 * LDK];
    __shared__ __align__(16) __nv_bfloat16 Bs[2][128 * LDK];

    const int tid  = threadIdx.x;
    const int wid  = tid >> 5;
    const int lane = tid & 31;
    const int wm   = wid >> 2;
    const int wn   = wid & 3;
    // n-tile on the FAST block index so CTAs sharing an A m-tile are co-scheduled
    const size_t m0 = (size_t)blockIdx.y * TILE_M;
    const int bn0   = blockIdx.x * 128;

    const uint32_t sA0 = smem_u32(As[0]);
    const uint32_t sA1 = smem_u32(As[1]);
    const uint32_t sB0 = smem_u32(Bs[0]);
    const uint32_t sB1 = smem_u32(Bs[1]);

    const int lrow8 = lane & 7;
    const int lmat  = lane >> 3;
    const int a_r = lrow8 + (lmat & 1) * 8;
    const int a_k = (lmat >> 1) * 8;
    const int b_n = lrow8 + (lmat >> 1) * 8;
    const int b_k = (lmat & 1) * 8;

    const uint32_t aoff = (uint32_t)((wm * 64 + a_r) * LDK + a_k) * 2;
    const uint32_t boff = (uint32_t)((wn * 32 + b_n) * LDK + b_k) * 2;

    float c[4][4][4];
    #pragma unroll
    for (int mi = 0; mi < 4; mi++)
        #pragma unroll
        for (int ni = 0; ni < 4; ni++)
            #pragma unroll
            for (int j = 0; j < 4; j++) c[mi][ni][j] = 0.f;

    fill_stage(0, m0, bn0, sA0, sB0, tid);

    for (int i = 0; i < NK; i++) {
        const int s = i & 1;
        if (i + 1 < NK) {
            fill_stage(i + 1, m0, bn0, s ? sA0 : sA1, s ? sB0 : sB1, tid);
            asm volatile("cp.async.wait_group 1;" ::: "memory");
        } else {
            asm volatile("cp.async.wait_group 0;" ::: "memory");
        }
        __syncthreads();

        const uint32_t cA = (s ? sA1 : sA0) + aoff;
        const uint32_t cB = (s ? sB1 : sB0) + boff;

        #pragma unroll
        for (int h = 0; h < 2; h++) {
            uint32_t a[4][4];
            uint32_t b[2][4];
            #pragma unroll
            for (int mi = 0; mi < 4; mi++)
                ldm_x4(a[mi][0], a[mi][1], a[mi][2], a[mi][3],
                       cA + h * 32 + (uint32_t)mi * (16 * LDK * 2));
            #pragma unroll
            for (int p = 0; p < 2; p++)
                ldm_x4(b[p][0], b[p][1], b[p][2], b[p][3],
                       cB + h * 32 + (uint32_t)p * (16 * LDK * 2));
            #pragma unroll
            for (int mi = 0; mi < 4; mi++) {
                #pragma unroll
                for (int ni = 0; ni < 4; ni++) {
                    uint32_t bb0 = (ni & 1) ? b[ni >> 1][2] : b[ni >> 1][0];
                    uint32_t bb1 = (ni & 1) ? b[ni >> 1][3] : b[ni >> 1][1];
                    mma_bf16(c[mi][ni][0], c[mi][ni][1], c[mi][ni][2], c[mi][ni][3],
                             a[mi][0], a[mi][1], a[mi][2], a[mi][3], bb0, bb1);
                }
            }
        }
        __syncthreads();
    }

    const int rr = lane >> 2;
    const int cc = (lane & 3) * 2;
    #pragma unroll
    for (int mi = 0; mi < 4; mi++) {
        size_t row0 = m0 + wm * 64 + mi * 16 + rr;
        #pragma unroll
        for (int ni = 0; ni < 4; ni++) {
            int col = bn0 + wn * 32 + ni * 8 + cc;
            if (row0 < N_NODES)
                *reinterpret_cast<float2*>(g_y1 + row0 * FILTERS + col) =
                    make_float2(c[mi][ni][0], c[mi][ni][1]);
            if (row0 + 8 < N_NODES)
                *reinterpret_cast<float2*>(g_y1 + (row0 + 8) * FILTERS + col) =
                    make_float2(c[mi][ni][2], c[mi][ni][3]);
        }
    }
}

// ---------------- CSR build ---------------------------------------------------
__global__ void csr_zero_kernel() {
    int i = blockIdx.x * blockDim.x + threadIdx.x;
    if (i < N_NODES) { g_deg[i] = 0; g_fill[i] = 0; }
}

__global__ void csr_hist_kernel(const int* __restrict__ edst, int E) {
    int e = (blockIdx.x * blockDim.x + threadIdx.x) * 4;
    if (e + 3 < E) {
        int4 d = *reinterpret_cast<const int4*>(edst + e);
        atomicAdd(&g_deg[d.x], 1);
        atomicAdd(&g_deg[d.y], 1);
        atomicAdd(&g_deg[d.z], 1);
        atomicAdd(&g_deg[d.w], 1);
    } else {
        for (; e < E; e++) atomicAdd(&g_deg[edst[e]], 1);
    }
}

__global__ __launch_bounds__(1024)
void csr_scan_kernel() {
    __shared__ int sums[1024];
    const int t = threadIdx.x;
    const int CH = (N_NODES + 1023) / 1024;
    int beg = t * CH;
    int end = min(beg + CH, N_NODES);
    int s = 0;
    for (int i = beg; i < end; i++) s += g_deg[i];
    sums[t] = s;
    __syncthreads();
    #pragma unroll
    for (int off = 1; off < 1024; off <<= 1) {
        int v = 0;
        if (t >= off) v = sums[t - off];
        __syncthreads();
        if (t >= off) sums[t] += v;
        __syncthreads();
    }
    int pre = (t == 0) ? 0 : sums[t - 1];
    for (int i = beg; i < end; i++) {
        int d = g_deg[i];
        g_rowptr[i] = pre;
        pre += d;
    }
    if (t == 1023) g_rowptr[N_NODES] = pre;
}

__global__ void csr_fill_kernel(const int* __restrict__ esrc, const int* __restrict__ edst,
                                const float* __restrict__ ew, int E) {
    int e = (blockIdx.x * blockDim.x + threadIdx.x) * 4;
    if (e + 3 < E) {
        int4   s = *reinterpret_cast<const int4*>(esrc + e);
        int4   d = *reinterpret_cast<const int4*>(edst + e);
        float4 w = *reinterpret_cast<const float4*>(ew + e);
        int p0 = g_rowptr[d.x] + atomicAdd(&g_fill[d.x], 1);
        g_csrc[p0] = s.x; g_cw[p0] = w.x;
        int p1 = g_rowptr[d.y] + atomicAdd(&g_fill[d.y], 1);
        g_csrc[p1] = s.y; g_cw[p1] = w.y;
        int p2 = g_rowptr[d.z] + atomicAdd(&g_fill[d.z], 1);
        g_csrc[p2] = s.z; g_cw[p2] = w.z;
        int p3 = g_rowptr[d.w] + atomicAdd(&g_fill[d.w], 1);
        g_csrc[p3] = s.w; g_cw[p3] = w.w;
    } else {
        for (; e < E; e++) {
            int d = edst[e];
            int pos = g_rowptr[d] + atomicAdd(&g_fill[d], 1);
            g_csrc[pos] = esrc[e];
            g_cw[pos]   = ew[e];
        }
    }
}

// ---------------- spmm1 as CSR gather: warp per dst, no atomics --------------
__global__ __launch_bounds__(256)
void spmm1_csr_kernel() {
    int dst = (blockIdx.x * blockDim.x + threadIdx.x) >> 5;
    int lane = threadIdx.x & 31;
    if (dst >= N_NODES) return;
    int e   = g_rowptr[dst];
    int end = g_rowptr[dst + 1];

    float4 a0 = make_float4(0.f, 0.f, 0.f, 0.f);
    float4 a1 = a0, b0 = a0, b1 = a0;

    for (; e + 1 < end; e += 2) {
        int   s0 = __ldg(g_csrc + e),     s1 = __ldg(g_csrc + e + 1);
        float w0 = __ldg(g_cw + e),       w1 = __ldg(g_cw + e + 1);
        const float4* r0 = reinterpret_cast<const float4*>(g_y1 + (size_t)s0 * FILTERS);
        const float4* r1 = reinterpret_cast<const float4*>(g_y1 + (size_t)s1 * FILTERS);
        float4 v00 = r0[lane], v01 = r0[lane + 32];
        float4 v10 = r1[lane], v11 = r1[lane + 32];
        a0.x += w0 * v00.x; a0.y += w0 * v00.y; a0.z += w0 * v00.z; a0.w += w0 * v00.w;
        a1.x += w0 * v01.x; a1.y += w0 * v01.y; a1.z += w0 * v01.z; a1.w += w0 * v01.w;
        b0.x += w1 * v10.x; b0.y += w1 * v10.y; b0.z += w1 * v10.z; b0.w += w1 * v10.w;
        b1.x += w1 * v11.x; b1.y += w1 * v11.y; b1.z += w1 * v11.z; b1.w += w1 * v11.w;
    }
    if (e < end) {
        int   s0 = __ldg(g_csrc + e);
        float w0 = __ldg(g_cw + e);
        const float4* r0 = reinterpret_cast<const float4*>(g_y1 + (size_t)s0 * FILTERS);
        float4 v00 = r0[lane], v01 = r0[lane + 32];
        a0.x += w0 * v00.x; a0.y += w0 * v00.y; a0.z += w0 * v00.z; a0.w += w0 * v00.w;
        a1.x += w0 * v01.x; a1.y += w0 * v01.y; a1.z += w0 * v01.z; a1.w += w0 * v01.w;
    }
    a0.x += b0.x; a0.y += b0.y; a0.z += b0.z; a0.w += b0.w;
    a1.x += b1.x; a1.y += b1.y; a1.z += b1.z; a1.w += b1.w;

    float4* o = reinterpret_cast<float4*>(g_acc1 + (size_t)dst * FILTERS);
    o[lane]      = a0;
    o[lane + 32] = a1;
}

// ---------------- GEMM2 fused with ReLU (vectorized) ------------------------
__global__ __launch_bounds__(256)
void gemm2_relu_kernel(const float* __restrict__ W2) {
    __shared__ float sW2[FILTERS * NCLS];
    __shared__ float4 sh4[16][64];

    const int tid = threadIdx.x;
    const int row0 = blockIdx.x * 16;

    for (int i = tid; i < FILTERS * NCLS; i += 256)
        sW2[i] = W2[i];

    #pragma unroll
    for (int t = 0; t < 4; t++) {
        int idx = tid + t * 256;
        int r = idx >> 6, f4 = idx & 63;
        int row = row0 + r;
        float4 v = make_float4(0.f, 0.f, 0.f, 0.f);
        if (row < N_NODES)
            v = *reinterpret_cast<const float4*>(g_acc1 + (size_t)row * FILTERS + f4 * 4);
        v.x = fmaxf(v.x, 0.f); v.y = fmaxf(v.y, 0.f);
        v.z = fmaxf(v.z, 0.f); v.w = fmaxf(v.w, 0.f);
        sh4[r][f4] = v;
    }
    __syncthreads();

    const int r = tid >> 4;
    const int c = tid & 15;
    float acc = 0.f;
    #pragma unroll 8
    for (int f4 = 0; f4 < 64; f4++) {
        float4 a = sh4[r][f4];
        int fb = f4 * 64 + c;
        acc += a.x * sW2[fb]      + a.y * sW2[fb + 16]
             + a.z * sW2[fb + 32] + a.w * sW2[fb + 48];
    }
    int row = row0 + r;
    if (row < N_NODES)
        g_y2[(size_t)row * NCLS + c] = acc;
}

// ---------------- spmm2 (CSR gather) + fused softmax -------------------------
__global__ __launch_bounds__(256)
void spmm2_softmax_kernel(float* __restrict__ out) {
    int hw  = (blockIdx.x * blockDim.x + threadIdx.x) >> 4;
    int l   = threadIdx.x & 15;
    if (hw >= N_NODES) return;
    int e   = g_rowptr[hw];
    int end = g_rowptr[hw + 1];

    float acc = 0.f;
    for (; e < end; e++) {
        int   s = __ldg(g_csrc + e);
        float w = __ldg(g_cw + e);
        acc += w * __ldg(g_y2 + (size_t)s * NCLS + l);
    }

    float m = acc;
    #pragma unroll
    for (int off = 8; off >= 1; off >>= 1)
        m = fmaxf(m, __shfl_xor_sync(0xFFFFFFFFu, m, off, 16));
    float ev = expf(acc - m);
    float sum = ev;
    #pragma unroll
    for (int off = 8; off >= 1; off >>= 1)
        sum += __shfl_xor_sync(0xFFFFFFFFu, sum, off, 16);
    out[(size_t)hw * NCLS + l] = ev / sum;
}

// ---------------- launch ------------------------------------------------------
extern "C" void kernel_launch(void* const* d_in, const int* in_sizes, int n_in,
                              void* d_out, int out_size) {
    const float* x   = (const float*)d_in[0];
    const float* W1  = (const float*)d_in[1];
    const float* W2  = (const float*)d_in[2];
    const float* ew  = (const float*)d_in[3];
    const int*   es  = (const int*)  d_in[4];
    const int*   ed  = (const int*)  d_in[5];
    const int E = in_sizes[3];
    float* out = (float*)d_out;

    // split X and W1^T into bf16 hi/lo
    {
        size_t n4 = ((size_t)N_PAD * D_FEAT) / 4;
        conv_x_kernel<<<(unsigned)((n4 + 255) / 256), 256>>>(x);
        conv_w1_kernel<<<(D_FEAT * FILTERS + 255) / 256, 256>>>(W1);
    }

    // CSR build (vectorized hist/fill)
    csr_zero_kernel<<<(N_NODES + 255) / 256, 256>>>();
    csr_hist_kernel<<<((E + 3) / 4 + 255) / 256, 256>>>(ed, E);
    csr_scan_kernel<<<1, 1024>>>();
    csr_fill_kernel<<<((E + 3) / 4 + 255) / 256, 256>>>(es, ed, ew, E);

    // GEMM1 on HMMA: y1 = Xhi@W1hi + Xhi@W1lo + Xlo@W1hi
    {
        dim3 grid(2, N_TILES);    // n fastest -> A-tile L2 reuse
        gemm1_mma_kernel<<<grid, 256>>>();
    }

    // layer-1 propagate: acc1 = A @ y1 (CSR gather, atomic-free)
    spmm1_csr_kernel<<<(N_NODES * 32 + 255) / 256, 256>>>();

    // GEMM2 + ReLU
    gemm2_relu_kernel<<<(N_NODES + 15) / 16, 256>>>(W2);

    // layer-2 propagate + softmax, single write of output
    spmm2_softmax_kernel<<<(N_NODES * 16 + 255) / 256, 256>>>(out);
}